// round 4
// baseline (speedup 1.0000x reference)
#include <cuda_runtime.h>
#include <cstdint>

#define DMODEL 2048
#define NB 144
#define NBPAD 145
#define BM 16
#define BK 16
#define KT_STEPS (DMODEL / BK)   // 128

// Scratch: S[N][144] = [s1 | s2 | qg] per token
__device__ float g_S[16384 * NB];

// ---------------------------------------------------------------------------
// Kernel 1: skinny GEMM  S = x @ [W1|W2|Wg]^T   fp32, packed f32x2 FMA.
// 128-thread CTAs, BM=16 -> grid=1024 -> ~28 warps/SM (latency hiding),
// single-buffer smem + register prefetch (R1-proven inner loop).
// ---------------------------------------------------------------------------
__global__ __launch_bounds__(128, 7) void pk_gemm(
    const float* __restrict__ x, const float* __restrict__ W1,
    const float* __restrict__ W2, const float* __restrict__ Wg) {
  __shared__ __align__(16) float  a_s[BK][BM + 2];     // [k][token]
  __shared__ __align__(16) float2 b_s[BK][NBPAD];      // [k][col] dup pairs

  const int tid = threadIdx.x;
  const int tbase = blockIdx.x * BM;

  // Load-role indices: thread owns rows n_j = q + 16j (j<9), k-pair kp.
  const int q = tid >> 3;            // 0..15
  const int kp = tid & 7;            // 0..7 -> k floats 2kp, 2kp+1
  // Row pointers: j<4 -> W1[q+16j]; j in 4..7 -> W2[q+16j-64]; j=8 -> Wg[q]
  const float* rowp[9];
#pragma unroll
  for (int j = 0; j < 9; j++) {
    const int n = q + 16 * j;
    rowp[j] = ((j < 4) ? (W1 + (size_t)n * DMODEL)
             : (j < 8) ? (W2 + (size_t)(n - 64) * DMODEL)
                       : (Wg + (size_t)(n - 128) * DMODEL)) + 2 * kp;
  }
  const float* arow = x + (size_t)(tbase + q) * DMODEL + 2 * kp;

  // Compute-role indices: 9 cols x 1 m-pair per thread.
  const int tx = tid & 15;           // n-group: cols 9tx..9tx+8
  const int my = tid >> 4;           // m-pair: tokens 2my, 2my+1
  const int n0 = tx * 9;

  unsigned long long acc[9];
#pragma unroll
  for (int j = 0; j < 9; j++) acc[j] = 0ull;

  // prologue: load stage 0 into regs
  float2 bv[9], av;
#pragma unroll
  for (int j = 0; j < 9; j++) bv[j] = *(const float2*)(rowp[j]);
  av = *(const float2*)(arow);

  for (int kt = 0; kt < KT_STEPS; kt++) {
    // commit regs to smem (dup pairs for B)
#pragma unroll
    for (int j = 0; j < 9; j++) {
      const int n = q + 16 * j;
      b_s[2 * kp][n]     = make_float2(bv[j].x, bv[j].x);
      b_s[2 * kp + 1][n] = make_float2(bv[j].y, bv[j].y);
    }
    a_s[2 * kp][q]     = av.x;
    a_s[2 * kp + 1][q] = av.y;
    __syncthreads();

    // prefetch next stage (LDG latency hidden under compute)
    if (kt + 1 < KT_STEPS) {
      const int koff = (kt + 1) * BK;
#pragma unroll
      for (int j = 0; j < 9; j++) bv[j] = *(const float2*)(rowp[j] + koff);
      av = *(const float2*)(arow + koff);
    }

    // compute: 16 k-steps x 9 FFMA2
#pragma unroll
    for (int kk = 0; kk < BK; kk++) {
      const unsigned long long a2 = *(const unsigned long long*)&a_s[kk][2 * my];
#pragma unroll
      for (int j = 0; j < 9; j++) {
        const unsigned long long b2 = *(const unsigned long long*)&b_s[kk][n0 + j];
        asm("fma.rn.f32x2 %0, %1, %2, %0;" : "+l"(acc[j]) : "l"(a2), "l"(b2));
      }
    }
    __syncthreads();
  }

  // epilogue: acc[j] = (token 2my, token 2my+1) at col n0+j
  const int mg = tbase + 2 * my;
#pragma unroll
  for (int j = 0; j < 9; j++) {
    g_S[(size_t)mg * NB + n0 + j]       = __uint_as_float((unsigned)acc[j]);
    g_S[(size_t)(mg + 1) * NB + n0 + j] = __uint_as_float((unsigned)(acc[j] >> 32));
  }
}

// ---------------------------------------------------------------------------
// Kernel 2: fused expand + top-8 + gate + softmax.
// Expand row built in smem, stored with ONE TMA bulk copy (kills the
// STG.128 issue-cost bottleneck measured in R3: 12 cyc/SMSP each).
// ---------------------------------------------------------------------------
__device__ __forceinline__ void insert8(float v, int idx, float* vals, int* idxs) {
  if (v < vals[7] || (v == vals[7] && idx >= idxs[7])) return;
  int p = 7;
  while (p > 0 && (v > vals[p - 1] || (v == vals[p - 1] && idx < idxs[p - 1]))) {
    vals[p] = vals[p - 1]; idxs[p] = idxs[p - 1]; --p;
  }
  vals[p] = v; idxs[p] = idx;
}

__global__ __launch_bounds__(128) void pk_finish(
    const float* __restrict__ G,
    float* __restrict__ out_idx, float* __restrict__ out_w,
    float* __restrict__ out_sc) {
  __shared__ __align__(16) float row[160];
  __shared__ __align__(16) float buf[4096];    // 16KB expand row
  const int tid = threadIdx.x;
  const int tok = blockIdx.x;

  if (tid < NB / 4)
    ((float4*)row)[tid] = ((const float4*)(g_S + (size_t)tok * NB))[tid];
  __syncthreads();

  // expand into smem
#pragma unroll
  for (int r = 0; r < 8; r++) {
    const int i = tid + 128 * r;
    const int a = i >> 7;            // wait: i in [0,1024) float4s
    // (recomputed below properly)
    (void)a;
  }
#pragma unroll
  for (int r = 0; r < 8; r++) {
    const int i = tid + 128 * r;     // float4 index 0..1023
    const int a = i >> 4;
    const int b4 = i & 15;
    const float s1 = row[a];
    const float4 s2 = *(const float4*)&row[64 + b4 * 4];
    ((float4*)buf)[i] = make_float4(s1 + s2.x, s1 + s2.y, s1 + s2.z, s1 + s2.w);
  }

  // serial top-k on thread 0 (overlaps with other blocks' memory traffic)
  if (tid == 0) {
    float v1[8], v2[8], cv[8];
    int i1[8], i2[8], ci[8];
#pragma unroll
    for (int t = 0; t < 8; t++) {
      v1[t] = v2[t] = cv[t] = -3.4e38f;
      i1[t] = i2[t] = ci[t] = 0x7fffffff;
    }
    for (int a = 0; a < 64; a++) insert8(row[a], a, v1, i1);
    for (int b = 0; b < 64; b++) insert8(row[64 + b], b, v2, i2);
    for (int ai = 0; ai < 8; ai++)
      for (int bi = 0; bi < 8; bi++)
        insert8(v1[ai] + v2[bi], i1[ai] * 64 + i2[bi], cv, ci);

    float comb[8];
    for (int t = 0; t < 8; t++) {
      const float4* grow = (const float4*)(G + (size_t)ci[t] * 16);
      float g = 0.f;
#pragma unroll
      for (int u = 0; u < 4; u++) {
        float4 gv = grow[u];
        const float* qv = row + 128 + u * 4;
        g += qv[0] * gv.x + qv[1] * gv.y + qv[2] * gv.z + qv[3] * gv.w;
      }
      comb[t] = cv[t] + g;
    }
    float mx = comb[0];
    for (int t = 1; t < 8; t++) mx = fmaxf(mx, comb[t]);
    float e[8], sum = 0.f;
    for (int t = 0; t < 8; t++) { e[t] = expf(comb[t] - mx); sum += e[t]; }
    const float inv = 1.f / sum;
    for (int t = 0; t < 8; t++) {
      out_idx[(size_t)tok * 8 + t] = (float)ci[t];
      out_w[(size_t)tok * 8 + t] = e[t] * inv;
    }
  }
  __syncthreads();

  // one TMA bulk store of the whole 16KB row
  if (tid == 0) {
    asm volatile("fence.proxy.async.shared::cta;" ::: "memory");
    unsigned saddr = (unsigned)__cvta_generic_to_shared(buf);
    const float* dst = out_sc + (size_t)tok * 4096;
    asm volatile(
        "cp.async.bulk.global.shared::cta.bulk_group [%0], [%1], %2;"
        :: "l"(dst), "r"(saddr), "n"(16384) : "memory");
    asm volatile("cp.async.bulk.commit_group;" ::: "memory");
    asm volatile("cp.async.bulk.wait_group 0;" ::: "memory");
  }
}

// ---------------------------------------------------------------------------
extern "C" void kernel_launch(void* const* d_in, const int* in_sizes, int n_in,
                              void* d_out, int out_size) {
  const float* x  = (const float*)d_in[0];
  const float* W1 = (const float*)d_in[1];
  const float* W2 = (const float*)d_in[2];
  const float* Wg = (const float*)d_in[3];
  const float* G  = (const float*)d_in[4];
  float* out = (float*)d_out;

  const int Ntok = in_sizes[0] / DMODEL;   // 16384

  float* out_idx = out;
  float* out_w   = out + (size_t)Ntok * 8;
  float* out_sc  = out + (size_t)Ntok * 16;

  pk_gemm<<<Ntok / BM, 128>>>(x, W1, W2, Wg);
  pk_finish<<<Ntok, 128>>>(G, out_idx, out_w, out_sc);
}

// round 7
// speedup vs baseline: 1.5429x; 1.5429x over previous
#include <cuda_runtime.h>
#include <cstdint>

#define DMODEL 2048
#define NB 144
#define BM 16
#define BK 16
#define KT_STEPS (DMODEL / BK)   // 128
#define TOK 64

// Scratch: S[N][144] = [s1 | s2 | qg] per token
__device__ __align__(16) float g_S[16384 * NB];

// ---------------------------------------------------------------------------
// Kernel 1: skinny GEMM  S = x @ [W1|W2|Wg]^T  fp32 packed f32x2.
// BM=16, grid=1024 (98.9% balance), 64 thr, occ 8 (16 warps/SM).
// n-packed accumulators: acc[p][j] = cols (2(9tx+j), +1) of row 2my+p.
// A-tile stride 18 float2 (144B) so the LDS.128 at [kk][2my] is 16B-aligned.
// ---------------------------------------------------------------------------
__global__ __launch_bounds__(64, 8) void pk_gemm(
    const float* __restrict__ x, const float* __restrict__ W1,
    const float* __restrict__ W2, const float* __restrict__ Wg) {
  __shared__ __align__(16) float2 a_s2[2][BK][18];  // dup-pairs {a,a} per row
  __shared__ __align__(16) float2 b_s2[2][BK][73];  // col pairs (2np,2np+1)

  const int tid = threadIdx.x;
  const int tbase = blockIdx.x * BM;

  // ---- load roles: thread owns float4 (4k) chunks ----
  const int k4 = tid & 3;           // 16B chunk along k
  const int lrow = tid >> 2;        // 0..15
  const float* bptr[9];
#pragma unroll
  for (int j = 0; j < 9; j++) {
    const int n = lrow + 16 * j;    // row 0..143
    const float* base = (j < 4) ? (W1 + (size_t)n * DMODEL)
                      : (j < 8) ? (W2 + (size_t)(n - 64) * DMODEL)
                                : (Wg + (size_t)(n - 128) * DMODEL);
    bptr[j] = base + 4 * k4;
  }
  const float* aptr = x + (size_t)(tbase + lrow) * DMODEL + 4 * k4;

  // ---- compute roles ----
  const int tx = tid & 7;           // n-pair group: np0 = 9*tx (cols 18tx..+17)
  const int my = tid >> 3;          // rows 2my, 2my+1
  const int np0 = 9 * tx;

  unsigned long long acc[2][9];
#pragma unroll
  for (int p = 0; p < 2; p++)
#pragma unroll
    for (int j = 0; j < 9; j++) acc[p][j] = 0ull;

  auto load_sts = [&](int kt, int s) {
    const int koff = kt * BK;
    float* bs = (float*)&b_s2[s][0][0];     // stride 146 floats per kk
#pragma unroll
    for (int j = 0; j < 9; j++) {
      const float4 v = *(const float4*)(bptr[j] + koff);
      const int n = lrow + 16 * j;
#pragma unroll
      for (int u = 0; u < 4; u++)
        bs[(4 * k4 + u) * 146 + n] = (&v.x)[u];
    }
    const float4 va = *(const float4*)(aptr + koff);
#pragma unroll
    for (int u = 0; u < 4; u++)
      a_s2[s][4 * k4 + u][lrow] = make_float2((&va.x)[u], (&va.x)[u]);
  };

  load_sts(0, 0);
  __syncthreads();

  for (int kt = 0; kt < KT_STEPS; kt++) {
    const int s = kt & 1;
    if (kt + 1 < KT_STEPS) load_sts(kt + 1, s ^ 1);

#pragma unroll
    for (int kk = 0; kk < BK; kk++) {
      // both m-rows' dup-pairs in one LDS.128 (16B-aligned: kk*144 + 16*my)
      const float4 af = *(const float4*)&a_s2[s][kk][2 * my];
      unsigned long long a0, a1;
      asm("mov.b64 %0, {%1, %2};" : "=l"(a0) : "f"(af.x), "f"(af.y));
      asm("mov.b64 %0, {%1, %2};" : "=l"(a1) : "f"(af.z), "f"(af.w));
#pragma unroll
      for (int j = 0; j < 9; j++) {
        const unsigned long long b2 =
            *(const unsigned long long*)&b_s2[s][kk][np0 + j];
        asm("fma.rn.f32x2 %0, %1, %2, %0;" : "+l"(acc[0][j]) : "l"(a0), "l"(b2));
        asm("fma.rn.f32x2 %0, %1, %2, %0;" : "+l"(acc[1][j]) : "l"(a1), "l"(b2));
      }
    }
    __syncthreads();
  }

  // epilogue: acc[p][j] -> g_S[row][2(np0+j)], 8B-aligned packed store
#pragma unroll
  for (int p = 0; p < 2; p++) {
    const size_t rbase = (size_t)(tbase + 2 * my + p) * NB;
#pragma unroll
    for (int j = 0; j < 9; j++)
      *(unsigned long long*)(g_S + rbase + 2 * (np0 + j)) = acc[p][j];
  }
}

// ---------------------------------------------------------------------------
// Kernel 2: top-8 + gate + softmax (R1-proven, fully token-parallel)
// ---------------------------------------------------------------------------
__device__ __forceinline__ void insert8(float v, int idx, float* vals, int* idxs) {
  if (v < vals[7] || (v == vals[7] && idx >= idxs[7])) return;
  int p = 7;
  while (p > 0 && (v > vals[p - 1] || (v == vals[p - 1] && idx < idxs[p - 1]))) {
    vals[p] = vals[p - 1]; idxs[p] = idxs[p - 1]; --p;
  }
  vals[p] = v; idxs[p] = idx;
}

__global__ __launch_bounds__(256, 1) void pk_topk(
    const float* __restrict__ G,
    float* __restrict__ out_idx, float* __restrict__ out_w) {
  __shared__ __align__(16) float s_s[TOK][NB + 4];
  const int tid = threadIdx.x;
  const int t0 = blockIdx.x * TOK;

  for (int i = tid; i < TOK * (NB / 4); i += 256) {
    int m = i / (NB / 4), c = i % (NB / 4);
    *(float4*)&s_s[m][c * 4] = *(const float4*)(g_S + (size_t)(t0 + m) * NB + c * 4);
  }
  __syncthreads();

  if (tid < TOK) {
    const float* r = s_s[tid];
    float v1[8], v2[8], cv[8];
    int i1[8], i2[8], ci[8];
#pragma unroll
    for (int t = 0; t < 8; t++) {
      v1[t] = v2[t] = cv[t] = -3.4e38f;
      i1[t] = i2[t] = ci[t] = 0x7fffffff;
    }
    for (int a = 0; a < 64; a++) insert8(r[a], a, v1, i1);
    for (int b = 0; b < 64; b++) insert8(r[64 + b], b, v2, i2);
    for (int ai = 0; ai < 8; ai++)
      for (int bi = 0; bi < 8; bi++)
        insert8(v1[ai] + v2[bi], i1[ai] * 64 + i2[bi], cv, ci);

    float comb[8];
    for (int t = 0; t < 8; t++) {
      const float* grow = G + (size_t)ci[t] * 16;
      float g = 0.f;
#pragma unroll
      for (int u = 0; u < 16; u++) g += r[128 + u] * grow[u];
      comb[t] = cv[t] + g;
    }
    float mx = comb[0];
    for (int t = 1; t < 8; t++) mx = fmaxf(mx, comb[t]);
    float e[8], sum = 0.f;
    for (int t = 0; t < 8; t++) { e[t] = expf(comb[t] - mx); sum += e[t]; }
    const float inv = 1.f / sum;
    const int gm = t0 + tid;
    for (int t = 0; t < 8; t++) {
      out_idx[gm * 8 + t] = (float)ci[t];
      out_w[gm * 8 + t] = e[t] * inv;
    }
  }
}

// ---------------------------------------------------------------------------
// Kernel 3: expand with PIPELINED TMA bulk stores (depth 2).
// 16 tokens per CTA; wait_group 1 only gates buffer reuse, never the epilogue
// of a single store. DRAM-write-bound by design.
// ---------------------------------------------------------------------------
__global__ __launch_bounds__(128) void pk_expand(float* __restrict__ out_sc) {
  __shared__ __align__(16) float row[160];
  __shared__ __align__(16) float buf[2][4096];   // 2 x 16KB
  const int tid = threadIdx.x;
  const int tok0 = blockIdx.x * 16;

  for (int t = 0; t < 16; t++) {
    const int s = t & 1;
    // gate reuse of buf[s]: store issued at t-2 must be complete
    if (t >= 2 && tid == 0)
      asm volatile("cp.async.bulk.wait_group 1;" ::: "memory");
    __syncthreads();   // wait visible to all; prev expand also done -> row free

    if (tid < 36)
      ((float4*)row)[tid] =
          ((const float4*)(g_S + (size_t)(tok0 + t) * NB))[tid];
    __syncthreads();   // row ready

#pragma unroll
    for (int r = 0; r < 8; r++) {
      const int i = tid + 128 * r;        // float4 idx 0..1023
      const int a = i >> 4;
      const int b4 = i & 15;
      const float s1 = row[a];
      const float4 s2 = *(const float4*)&row[64 + 4 * b4];
      ((float4*)buf[s])[i] =
          make_float4(s1 + s2.x, s1 + s2.y, s1 + s2.z, s1 + s2.w);
    }
    __syncthreads();   // buf[s] complete

    if (tid == 0) {
      asm volatile("fence.proxy.async.shared::cta;" ::: "memory");
      unsigned saddr = (unsigned)__cvta_generic_to_shared(buf[s]);
      const float* dst = out_sc + (size_t)(tok0 + t) * 4096;
      asm volatile(
          "cp.async.bulk.global.shared::cta.bulk_group [%0], [%1], %2;"
          :: "l"(dst), "r"(saddr), "n"(16384) : "memory");
      asm volatile("cp.async.bulk.commit_group;" ::: "memory");
    }
  }
  // CTA must not exit while TMA still reads smem
  if (tid == 0)
    asm volatile("cp.async.bulk.wait_group 0;" ::: "memory");
}

// ---------------------------------------------------------------------------
extern "C" void kernel_launch(void* const* d_in, const int* in_sizes, int n_in,
                              void* d_out, int out_size) {
  const float* x  = (const float*)d_in[0];
  const float* W1 = (const float*)d_in[1];
  const float* W2 = (const float*)d_in[2];
  const float* Wg = (const float*)d_in[3];
  const float* G  = (const float*)d_in[4];
  float* out = (float*)d_out;

  const int Ntok = in_sizes[0] / DMODEL;   // 16384

  float* out_idx = out;
  float* out_w   = out + (size_t)Ntok * 8;
  float* out_sc  = out + (size_t)Ntok * 16;

  pk_gemm<<<Ntok / BM, 64>>>(x, W1, W2, Wg);
  pk_topk<<<Ntok / TOK, 256>>>(G, out_idx, out_w);
  pk_expand<<<Ntok / 16, 128>>>(out_sc);
}

// round 8
// speedup vs baseline: 2.1445x; 1.3899x over previous
#include <cuda_runtime.h>
#include <cstdint>

#define DMODEL 2048
#define NTOK_CTA 16

// Arena float offsets:
//  gemm:   sB[2][144][20] at 0      (5760 floats; row stride 20 floats = 80B)
//          sA[2][16][20]  at 5760   (640 floats)
//  epilogue (aliased after sync):
//          S[16][160]     at 0      (2560 floats)
//          s1T[16][64]    at 2560   (1024 floats)
#define SB_OFF(s, n, f)  ((s) * 2880 + (n) * 20 + (f))
#define SA_OFF(s, t, f)  (5760 + (s) * 320 + (t) * 20 + (f))
#define S_OFF(t, n)      ((t) * 160 + (n))
#define S1T_OFF(t, i)    (2560 + (t) * 64 + (i))

__device__ __forceinline__ void cp16(unsigned saddr, const void* g) {
  asm volatile("cp.async.cg.shared.global [%0], [%1], 16;" :: "r"(saddr), "l"(g));
}

// Tie-aware sorted insert: (value desc, index asc) == jax.lax.top_k order
__device__ __forceinline__ void insert8(float v, int idx, float* vals, int* idxs) {
  if (v < vals[7] || (v == vals[7] && idx >= idxs[7])) return;
  int p = 7;
  while (p > 0 && (v > vals[p - 1] || (v == vals[p - 1] && idx < idxs[p - 1]))) {
    vals[p] = vals[p - 1]; idxs[p] = idxs[p - 1]; --p;
  }
  vals[p] = v; idxs[p] = idx;
}

// ---------------------------------------------------------------------------
// One fused kernel: skinny GEMM (k-packed f32x2) -> expand stores -> topk.
// grid = 1024 CTAs x 64 thr, occ 7 -> single wave, 98.9% SM balance.
// ---------------------------------------------------------------------------
__global__ __launch_bounds__(64, 7) void pk_fused(
    const float* __restrict__ x, const float* __restrict__ W1,
    const float* __restrict__ W2, const float* __restrict__ Wg,
    const float* __restrict__ G,
    float* __restrict__ out_idx, float* __restrict__ out_w,
    float* __restrict__ out_sc) {
  __shared__ __align__(16) float arena[6400];
  const int tid = threadIdx.x;
  const int tok0 = blockIdx.x * NTOK_CTA;
  const unsigned sbase = (unsigned)__cvta_generic_to_shared(arena);

  // ---- loader roles: thread owns one 16B chunk of 10 rows ----
  const int n0L = tid >> 2;             // 0..15
  const int c4 = (tid & 3) * 4;         // float offset of 16B chunk
  const float* pW1 = W1 + (size_t)n0L * DMODEL + c4;
  const float* pW2 = W2 + (size_t)n0L * DMODEL + c4;
  const float* pWg = Wg + (size_t)n0L * DMODEL + c4;
  const float* pA  = x + (size_t)(tok0 + n0L) * DMODEL + c4;

  // ---- compute roles: 2 warps = col halves; lane = 4 mg x 8 ng ----
  const int nh = tid >> 5;
  const int lane = tid & 31;
  const int mg = lane >> 3;             // tokens 4mg..4mg+3
  const int ng = lane & 7;              // cols n0..n0+8
  const int n0 = 72 * nh + 9 * ng;
  const int t0 = 4 * mg;

  unsigned long long acc[4][9];         // f32x2: lo = even-k partial, hi = odd-k
#pragma unroll
  for (int m = 0; m < 4; m++)
#pragma unroll
    for (int j = 0; j < 9; j++) acc[m][j] = 0ull;

  auto load_stage = [&](int kt, int s) {
    const int ko = kt * 16;
#pragma unroll
    for (int j = 0; j < 9; j++) {
      const float* src = (j < 4) ? (pW1 + j * 16 * DMODEL + ko)
                       : (j < 8) ? (pW2 + (j - 4) * 16 * DMODEL + ko)
                                 : (pWg + ko);
      cp16(sbase + 4u * SB_OFF(s, n0L + 16 * j, c4), src);
    }
    cp16(sbase + 4u * SA_OFF(s, n0L, c4), pA + ko);
  };

  load_stage(0, 0);
  asm volatile("cp.async.commit_group;" ::: "memory");
  load_stage(1, 1);
  asm volatile("cp.async.commit_group;" ::: "memory");

  for (int kt = 0; kt < 128; kt++) {
    asm volatile("cp.async.wait_group 1;" ::: "memory");
    __syncthreads();
    const int s = kt & 1;

#pragma unroll
    for (int d = 0; d < 4; d++) {       // 2 k2-pairs (4 k) per step
      ulonglong2 la[4];
#pragma unroll
      for (int m = 0; m < 4; m++)
        la[m] = *(const ulonglong2*)&arena[SA_OFF(s, t0 + m, 4 * d)];
#pragma unroll
      for (int j = 0; j < 9; j++) {
        const ulonglong2 lb = *(const ulonglong2*)&arena[SB_OFF(s, n0 + j, 4 * d)];
#pragma unroll
        for (int m = 0; m < 4; m++) {
          asm("fma.rn.f32x2 %0, %1, %2, %0;"
              : "+l"(acc[m][j]) : "l"(la[m].x), "l"(lb.x));
          asm("fma.rn.f32x2 %0, %1, %2, %0;"
              : "+l"(acc[m][j]) : "l"(la[m].y), "l"(lb.y));
        }
      }
    }
    __syncthreads();

    if (kt + 2 < 128) load_stage(kt + 2, s);
    asm volatile("cp.async.commit_group;" ::: "memory");  // empty pad keeps wait_group 1 exact
  }
  asm volatile("cp.async.wait_group 0;" ::: "memory");
  __syncthreads();   // arena free for reuse

  // ---- epilogue: S[t][n] = acc.lo + acc.hi; build s1T transpose for expand ----
#pragma unroll
  for (int m = 0; m < 4; m++) {
    const int t = t0 + m;
#pragma unroll
    for (int j = 0; j < 9; j++) {
      const int n = n0 + j;
      float lo = __uint_as_float((unsigned)acc[m][j]);
      float hi = __uint_as_float((unsigned)(acc[m][j] >> 32));
      const float val = lo + hi;
      arena[S_OFF(t, n)] = val;
      if (n < 64)  // s1T[t][(n&3)*16 + (n>>2)] -> contiguous per expand thread
        arena[S1T_OFF(t, (n & 3) * 16 + (n >> 2))] = val;
    }
  }
  __syncthreads();

  // ---- expand: 256 MB streaming stores; out[i][a*64+b] = s1[a] + s2[b] ----
  const int bb = tid & 15;              // b float4 index (constant per thread)
  const int cc = tid >> 4;              // a residue class
#pragma unroll 1
  for (int t = 0; t < NTOK_CTA; t++) {
    const float4 s2v = *(const float4*)&arena[S_OFF(t, 64 + 4 * bb)];
    float4 s1a[4];
#pragma unroll
    for (int u = 0; u < 4; u++)
      s1a[u] = *(const float4*)&arena[S1T_OFF(t, cc * 16 + 4 * u)];
    float4* dst = (float4*)out_sc + ((size_t)(tok0 + t) << 10) + tid;
#pragma unroll
    for (int r = 0; r < 16; r++) {      // a = cc + 4r, float4 idx = tid + 64r
      const float s1 = ((const float*)s1a)[r];
      __stcs(dst + (r << 6),
             make_float4(s1 + s2v.x, s1 + s2v.y, s1 + s2v.z, s1 + s2v.w));
    }
  }

  // ---- topk + gate + softmax: threads 0..15, one token each ----
  if (tid < NTOK_CTA) {
    const float* r = &arena[S_OFF(tid, 0)];
    float v1[8], v2[8], cv[8];
    int i1[8], i2[8], ci[8];
#pragma unroll
    for (int q = 0; q < 8; q++) {
      v1[q] = v2[q] = cv[q] = -3.4e38f;
      i1[q] = i2[q] = ci[q] = 0x7fffffff;
    }
    for (int a = 0; a < 64; a++) insert8(r[a], a, v1, i1);
    for (int b = 0; b < 64; b++) insert8(r[64 + b], b, v2, i2);
    for (int ai = 0; ai < 8; ai++)
      for (int bi = 0; bi < 8; bi++)
        insert8(v1[ai] + v2[bi], i1[ai] * 64 + i2[bi], cv, ci);

    float comb[8];
    for (int q = 0; q < 8; q++) {
      const float4* grow = (const float4*)(G + (size_t)ci[q] * 16);
      float g = 0.f;
#pragma unroll
      for (int u = 0; u < 4; u++) {
        const float4 gv = grow[u];
        const float* qv = r + 128 + u * 4;
        g += qv[0] * gv.x + qv[1] * gv.y + qv[2] * gv.z + qv[3] * gv.w;
      }
      comb[q] = cv[q] + g;
    }
    float mx = comb[0];
    for (int q = 1; q < 8; q++) mx = fmaxf(mx, comb[q]);
    float e[8], sum = 0.f;
    for (int q = 0; q < 8; q++) { e[q] = expf(comb[q] - mx); sum += e[q]; }
    const float inv = 1.f / sum;
    const size_t gm = (size_t)(tok0 + tid) * 8;
    for (int q = 0; q < 8; q++) {
      out_idx[gm + q] = (float)ci[q];
      out_w[gm + q] = e[q] * inv;
    }
  }
}

// ---------------------------------------------------------------------------
extern "C" void kernel_launch(void* const* d_in, const int* in_sizes, int n_in,
                              void* d_out, int out_size) {
  const float* x  = (const float*)d_in[0];
  const float* W1 = (const float*)d_in[1];
  const float* W2 = (const float*)d_in[2];
  const float* Wg = (const float*)d_in[3];
  const float* G  = (const float*)d_in[4];
  float* out = (float*)d_out;

  const int Ntok = in_sizes[0] / DMODEL;   // 16384

  float* out_idx = out;
  float* out_w   = out + (size_t)Ntok * 8;
  float* out_sc  = out + (size_t)Ntok * 16;

  pk_fused<<<Ntok / NTOK_CTA, 64>>>(x, W1, W2, Wg, G, out_idx, out_w, out_sc);
}

// round 13
// speedup vs baseline: 2.1715x; 1.0126x over previous
#include <cuda_runtime.h>
#include <cstdint>

#define DMODEL 2048
#define NTOK 16
#define STAGE 3200
// arena: stage s = [ B: 144 rows x 20 floats | A: 16 rows x 20 floats ]
#define SB_OFF(s, n, f)  ((s) * STAGE + (n) * 20 + (f))
#define SA_OFF(s, t, f)  ((s) * STAGE + 2880 + (t) * 20 + (f))
#define S_OFF(t, n)      ((t) * 160 + (n))

__device__ __forceinline__ void cp16(unsigned saddr, const void* g) {
  asm volatile("cp.async.cg.shared.global [%0], [%1], 16;" :: "r"(saddr), "l"(g));
}

// Tie-aware sorted insert: (value desc, index asc) == jax.lax.top_k order
__device__ __forceinline__ void insert8(float v, int idx, float* vals, int* idxs) {
  if (v < vals[7] || (v == vals[7] && idx >= idxs[7])) return;
  int p = 7;
  while (p > 0 && (v > vals[p - 1] || (v == vals[p - 1] && idx < idxs[p - 1]))) {
    vals[p] = vals[p - 1]; idxs[p] = idxs[p - 1]; --p;
  }
  vals[p] = v; idxs[p] = idx;
}

// ---------------------------------------------------------------------------
// Fused: skinny GEMM (k-packed f32x2) -> expand stores -> topk/gate/softmax.
// grid 1024 x 96 thr, occ 7 -> 21 warps/SM (5.25/SMSP), all-resident.
// Loader = R8's proven static 64-thread pattern (no local pointer arrays).
// ---------------------------------------------------------------------------
__global__ __launch_bounds__(96, 7) void pk_fused(
    const float* __restrict__ x, const float* __restrict__ W1,
    const float* __restrict__ W2, const float* __restrict__ Wg,
    const float* __restrict__ G,
    float* __restrict__ out_idx, float* __restrict__ out_w,
    float* __restrict__ out_sc) {
  __shared__ __align__(16) float arena[6400];
  const int tid = threadIdx.x;
  const int tok0 = blockIdx.x * NTOK;
  const unsigned sbase = (unsigned)__cvta_generic_to_shared(arena);

  // ---- loader roles (threads 0..63): one 16B chunk of 10 rows each ----
  const int n0L = (tid & 63) >> 2;          // 0..15
  const int c4 = (tid & 3) * 4;             // float offset of 16B chunk
  const float* pW1 = W1 + (size_t)n0L * DMODEL + c4;
  const float* pW2 = W2 + (size_t)n0L * DMODEL + c4;
  const float* pWg = Wg + (size_t)n0L * DMODEL + c4;
  const float* pA  = x + (size_t)(tok0 + n0L) * DMODEL + c4;

  // ---- compute roles: warp w = cols [48w,48w+48); lane = 4mg x 8ng ----
  const int w = tid >> 5, lane = tid & 31;
  const int mg = lane >> 3, ng = lane & 7;  // tokens 4mg..4mg+3; col +ng

  unsigned long long acc[4][6];             // f32x2: even/odd-k partials
#pragma unroll
  for (int m = 0; m < 4; m++)
#pragma unroll
    for (int q = 0; q < 6; q++) acc[m][q] = 0ull;

  auto issue_loads = [&](int kt, int s) {
    if (tid < 64) {
      const int ko = kt * 16;
#pragma unroll
      for (int j = 0; j < 9; j++) {
        const float* src = (j < 4) ? (pW1 + j * 16 * DMODEL + ko)
                         : (j < 8) ? (pW2 + (j - 4) * 16 * DMODEL + ko)
                                   : (pWg + ko);
        cp16(sbase + 4u * SB_OFF(s, n0L + 16 * j, c4), src);
      }
      cp16(sbase + 4u * SA_OFF(s, n0L, c4), pA + ko);
    }
  };

  issue_loads(0, 0);
  asm volatile("cp.async.commit_group;" ::: "memory");
  issue_loads(1, 1);
  asm volatile("cp.async.commit_group;" ::: "memory");

  for (int kt = 0; kt < 128; kt++) {
    asm volatile("cp.async.wait_group 1;" ::: "memory");
    __syncthreads();
    const int s = kt & 1;

#pragma unroll
    for (int d = 0; d < 4; d++) {           // 4 k per d-step
      ulonglong2 la[4];
#pragma unroll
      for (int m = 0; m < 4; m++)
        la[m] = *(const ulonglong2*)&arena[SA_OFF(s, 4 * mg + m, 4 * d)];
#pragma unroll
      for (int q = 0; q < 6; q++) {
        const ulonglong2 lb =
            *(const ulonglong2*)&arena[SB_OFF(s, 48 * w + 8 * q + ng, 4 * d)];
#pragma unroll
        for (int m = 0; m < 4; m++) {
          asm("fma.rn.f32x2 %0, %1, %2, %0;"
              : "+l"(acc[m][q]) : "l"(la[m].x), "l"(lb.x));
          asm("fma.rn.f32x2 %0, %1, %2, %0;"
              : "+l"(acc[m][q]) : "l"(la[m].y), "l"(lb.y));
        }
      }
    }
    __syncthreads();

    if (kt + 2 < 128) issue_loads(kt + 2, s);
    asm volatile("cp.async.commit_group;" ::: "memory");  // keeps group count exact
  }
  asm volatile("cp.async.wait_group 0;" ::: "memory");
  __syncthreads();

  // ---- epilogue: S[t][n] = lo + hi into arena (stage-0 region, now dead) ----
#pragma unroll
  for (int m = 0; m < 4; m++) {
    const int t = 4 * mg + m;
#pragma unroll
    for (int q = 0; q < 6; q++) {
      const int n = 48 * w + 8 * q + ng;
      const float lo = __uint_as_float((unsigned)acc[m][q]);
      const float hi = __uint_as_float((unsigned)(acc[m][q] >> 32));
      arena[S_OFF(t, n)] = lo + hi;
    }
  }
  __syncthreads();

  // ---- expand: out[t][64a+b] = s1[a] + s2[b], streaming stores ----
  for (int t = 0; t < NTOK; t++) {
    float4* dst = (float4*)out_sc + ((size_t)(tok0 + t) << 10);
    const float* r = &arena[S_OFF(t, 0)];
    for (int i = tid; i < 1024; i += 96) {
      const int a = i >> 4, b = i & 15;
      const float s1 = r[a];
      const float4 s2 = *(const float4*)&r[64 + 4 * b];
      __stcs(dst + i, make_float4(s1 + s2.x, s1 + s2.y, s1 + s2.z, s1 + s2.w));
    }
  }

  // ---- topk + gate + softmax: threads 0..15, one token each ----
  if (tid < NTOK) {
    const float* r = &arena[S_OFF(tid, 0)];
    float v1[8], v2[8], cv[8];
    int i1[8], i2[8], ci[8];
#pragma unroll
    for (int q = 0; q < 8; q++) {
      v1[q] = v2[q] = cv[q] = -3.4e38f;
      i1[q] = i2[q] = ci[q] = 0x7fffffff;
    }
    for (int a = 0; a < 64; a++) insert8(r[a], a, v1, i1);
    for (int b = 0; b < 64; b++) insert8(r[64 + b], b, v2, i2);
    for (int ai = 0; ai < 8; ai++)
      for (int bi = 0; bi < 8; bi++)
        insert8(v1[ai] + v2[bi], i1[ai] * 64 + i2[bi], cv, ci);

    float comb[8];
    for (int q = 0; q < 8; q++) {
      const float4* grow = (const float4*)(G + (size_t)ci[q] * 16);
      float g = 0.f;
#pragma unroll
      for (int u = 0; u < 4; u++) {
        const float4 gv = grow[u];
        const float* qv = r + 128 + u * 4;
        g += qv[0] * gv.x + qv[1] * gv.y + qv[2] * gv.z + qv[3] * gv.w;
      }
      comb[q] = cv[q] + g;
    }
    float mx = comb[0];
    for (int q = 1; q < 8; q++) mx = fmaxf(mx, comb[q]);
    float e[8], sum = 0.f;
    for (int q = 0; q < 8; q++) { e[q] = expf(comb[q] - mx); sum += e[q]; }
    const float inv = 1.f / sum;
    const size_t gm = (size_t)(tok0 + tid) * 8;
    for (int q = 0; q < 8; q++) {
      out_idx[gm + q] = (float)ci[q];
      out_w[gm + q] = e[q] * inv;
    }
  }
}

// ---------------------------------------------------------------------------
extern "C" void kernel_launch(void* const* d_in, const int* in_sizes, int n_in,
                              void* d_out, int out_size) {
  const float* x  = (const float*)d_in[0];
  const float* W1 = (const float*)d_in[1];
  const float* W2 = (const float*)d_in[2];
  const float* Wg = (const float*)d_in[3];
  const float* G  = (const float*)d_in[4];
  float* out = (float*)d_out;

  const int Ntok = in_sizes[0] / DMODEL;   // 16384

  float* out_idx = out;
  float* out_w   = out + (size_t)Ntok * 8;
  float* out_sc  = out + (size_t)Ntok * 16;

  pk_fused<<<Ntok / NTOK, 96>>>(x, W1, W2, Wg, G, out_idx, out_w, out_sc);
}